// round 4
// baseline (speedup 1.0000x reference)
#include <cuda_runtime.h>

#define NB 8
#define NS 1024
#define ND 1024
#define NH 16
#define NHD 64

// 32 MB each — static device scratch (no runtime allocation).
static __device__ float g_q[(size_t)NB * NH * NS * NHD];
static __device__ float g_k[(size_t)NB * NH * NS * NHD];
static __device__ float g_v[(size_t)NB * NH * NS * NHD];

// ---------------------------------------------------------------------------
// QKV projection: Y = X @ W, output scattered to [b, h, s, hd] layout.
// 128x128 output tile, BK=16, 256 threads, 8x8 register microtile.
// gridDim.z in {0,1,2} selects (Wq->g_q, Wk->g_k, Wv->g_v).
// ---------------------------------------------------------------------------
__global__ __launch_bounds__(256, 2)
void qkv_gemm(const float* __restrict__ X, const float* __restrict__ Wq,
              const float* __restrict__ Wk, const float* __restrict__ Wv) {
    __shared__ __align__(16) float As[16][128];  // A tile, transposed [k][m]
    __shared__ __align__(16) float Bs[16][128];  // B tile, natural    [k][n]

    const float* W;
    float* dst;
    if (blockIdx.z == 0)      { W = Wq; dst = g_q; }
    else if (blockIdx.z == 1) { W = Wk; dst = g_k; }
    else                      { W = Wv; dst = g_v; }

    const int m0 = blockIdx.y * 128;
    const int n0 = blockIdx.x * 128;
    const int tid = threadIdx.x;
    const int ty = tid >> 4;        // 0..15 -> 8 output rows each
    const int tx = tid & 15;        // 0..15 -> 8 output cols each

    const int am = tid >> 2;        // 0..63  (A tile row, +64 second half)
    const int ak = (tid & 3) << 2;  // 0,4,8,12
    const int bk = tid >> 5;        // 0..7   (B tile row, +8 second half)
    const int bn = (tid & 31) << 2; // 0..124

    float acc[8][8];
#pragma unroll
    for (int i = 0; i < 8; ++i)
#pragma unroll
        for (int j = 0; j < 8; ++j) acc[i][j] = 0.0f;

    for (int k0 = 0; k0 < ND; k0 += 16) {
        float4 a0 = *(const float4*)(X + (size_t)(m0 + am) * ND + k0 + ak);
        float4 a1 = *(const float4*)(X + (size_t)(m0 + am + 64) * ND + k0 + ak);
        float4 b0 = *(const float4*)(W + (size_t)(k0 + bk) * ND + n0 + bn);
        float4 b1 = *(const float4*)(W + (size_t)(k0 + bk + 8) * ND + n0 + bn);
        __syncthreads();
        As[ak + 0][am] = a0.x; As[ak + 1][am] = a0.y;
        As[ak + 2][am] = a0.z; As[ak + 3][am] = a0.w;
        As[ak + 0][am + 64] = a1.x; As[ak + 1][am + 64] = a1.y;
        As[ak + 2][am + 64] = a1.z; As[ak + 3][am + 64] = a1.w;
        *(float4*)&Bs[bk][bn]     = b0;
        *(float4*)&Bs[bk + 8][bn] = b1;
        __syncthreads();
#pragma unroll
        for (int kk = 0; kk < 16; ++kk) {
            float4 av0 = *(const float4*)&As[kk][ty * 8];
            float4 av1 = *(const float4*)&As[kk][ty * 8 + 4];
            float4 bv0 = *(const float4*)&Bs[kk][tx * 8];
            float4 bv1 = *(const float4*)&Bs[kk][tx * 8 + 4];
            float aa[8] = {av0.x, av0.y, av0.z, av0.w, av1.x, av1.y, av1.z, av1.w};
            float bb[8] = {bv0.x, bv0.y, bv0.z, bv0.w, bv1.x, bv1.y, bv1.z, bv1.w};
#pragma unroll
            for (int i = 0; i < 8; ++i)
#pragma unroll
                for (int j = 0; j < 8; ++j)
                    acc[i][j] = fmaf(aa[i], bb[j], acc[i][j]);
        }
    }

    // Epilogue: scatter to [b, h, s, hd]. Each thread's 8 cols live in one head.
#pragma unroll
    for (int i = 0; i < 8; ++i) {
        const int m  = m0 + ty * 8 + i;
        const int bi = m >> 10;
        const int s  = m & (NS - 1);
        const int n  = n0 + tx * 8;
        const int h  = n >> 6;
        const int hd = n & (NHD - 1);
        float* o = dst + ((((size_t)bi * NH + h) * NS + s) * NHD + hd);
        *(float4*)(o)     = make_float4(acc[i][0], acc[i][1], acc[i][2], acc[i][3]);
        *(float4*)(o + 4) = make_float4(acc[i][4], acc[i][5], acc[i][6], acc[i][7]);
    }
}

// ---------------------------------------------------------------------------
// Fused attention: one block per (b, h, 64-query tile). Streams 64-key tiles:
//   S = Q K^T / 8  ->  P = exp(S) * mask  ->  O += P V, rowsum += P
// Final: out = O / (rowsum + 1e-8), written to [b, s, h*64+hd].
// 128 threads; microtiles 4(q) x 8(cols). 48 KB static smem.
// ---------------------------------------------------------------------------
__global__ __launch_bounds__(128, 4)
void attn_fused(const float* __restrict__ mask, float* __restrict__ out) {
    __shared__ __align__(16) float Qs[64 * 64];   // [d][q] (transposed)
    __shared__ __align__(16) float KVs[64 * 64];  // phase 1: K [d][t]; phase 2: V [t][d]
    __shared__ __align__(16) float Pt[64 * 64];   // [t][q] (transposed P)

    const int qt  = blockIdx.x;   // query tile 0..15
    const int h   = blockIdx.y;
    const int b   = blockIdx.z;
    const int tid = threadIdx.x;
    const int ty  = tid >> 3;     // 0..15 -> 4 query rows each
    const int tx  = tid & 7;      // 0..7  -> 8 cols each

    const size_t bh = (size_t)b * NH + h;
    const float* qp   = g_q + (bh * NS + (size_t)qt * 64) * NHD;
    const float* kb   = g_k + bh * NS * NHD;
    const float* vb   = g_v + bh * NS * NHD;
    const float* mrow = mask + ((size_t)b * NS + (size_t)qt * 64) * NS;

    // Load Q tile transposed into smem (once per block).
    for (int it = tid; it < 1024; it += 128) {
        const int q = it >> 4;
        const int d = (it & 15) << 2;
        float4 v = *(const float4*)(qp + (size_t)q * NHD + d);
        Qs[(d + 0) * 64 + q] = v.x;
        Qs[(d + 1) * 64 + q] = v.y;
        Qs[(d + 2) * 64 + q] = v.z;
        Qs[(d + 3) * 64 + q] = v.w;
    }

    float acc[4][8];
#pragma unroll
    for (int i = 0; i < 4; ++i)
#pragma unroll
        for (int j = 0; j < 8; ++j) acc[i][j] = 0.0f;
    float rs[4] = {0.0f, 0.0f, 0.0f, 0.0f};

    for (int kt = 0; kt < 16; ++kt) {
        const float* kp = kb + (size_t)kt * 64 * NHD;
        __syncthreads();  // prior-iteration Ps/V reads complete
        // K tile transposed into smem. Lane-varying t => conflict-free stores
        // (costs strided global reads; K tiles are small and L2-resident).
        for (int it = tid; it < 1024; it += 128) {
            const int t = it & 63;
            const int d = (it >> 6) << 2;
            float4 v = *(const float4*)(kp + (size_t)t * NHD + d);
            KVs[(d + 0) * 64 + t] = v.x;
            KVs[(d + 1) * 64 + t] = v.y;
            KVs[(d + 2) * 64 + t] = v.z;
            KVs[(d + 3) * 64 + t] = v.w;
        }
        __syncthreads();

        // S = Q K^T  (contraction over d)
        float sacc[4][8];
#pragma unroll
        for (int i = 0; i < 4; ++i)
#pragma unroll
            for (int j = 0; j < 8; ++j) sacc[i][j] = 0.0f;

#pragma unroll 8
        for (int d = 0; d < 64; ++d) {
            float aa[4];
#pragma unroll
            for (int i = 0; i < 4; ++i) aa[i] = Qs[d * 64 + ty * 4 + i];
            float4 bv0 = *(const float4*)&KVs[d * 64 + tx * 8];
            float4 bv1 = *(const float4*)&KVs[d * 64 + tx * 8 + 4];
            float bb[8] = {bv0.x, bv0.y, bv0.z, bv0.w, bv1.x, bv1.y, bv1.z, bv1.w};
#pragma unroll
            for (int i = 0; i < 4; ++i)
#pragma unroll
                for (int j = 0; j < 8; ++j)
                    sacc[i][j] = fmaf(aa[i], bb[j], sacc[i][j]);
        }
        __syncthreads();  // K reads done; KVs free for V

        // Load V tile (natural [t][d], coalesced).
        const float* vp = vb + (size_t)kt * 64 * NHD;
        for (int it = tid; it < 1024; it += 128) {
            const int t = it >> 4;
            const int d = (it & 15) << 2;
            *(float4*)&KVs[t * 64 + d] = *(const float4*)(vp + (size_t)t * NHD + d);
        }

        // P = exp(S/8) * mask  -> Pt (transposed), accumulate row sums.
#pragma unroll
        for (int i = 0; i < 4; ++i) {
            const int q = ty * 4 + i;
            const float* mp = mrow + (size_t)q * NS + kt * 64 + tx * 8;
            float4 m0 = *(const float4*)(mp);
            float4 m1 = *(const float4*)(mp + 4);
            float mm[8] = {m0.x, m0.y, m0.z, m0.w, m1.x, m1.y, m1.z, m1.w};
            float p[8];
#pragma unroll
            for (int j = 0; j < 8; ++j)
                p[j] = __expf(sacc[i][j] * 0.125f) * mm[j];
            rs[i] += ((p[0] + p[1]) + (p[2] + p[3])) + ((p[4] + p[5]) + (p[6] + p[7]));
#pragma unroll
            for (int j = 0; j < 8; ++j)
                Pt[(tx * 8 + j) * 64 + q] = p[j];
        }
        __syncthreads();  // Pt + V visible

        // O += P V  (contraction over t)
#pragma unroll 8
        for (int t = 0; t < 64; ++t) {
            float aa[4];
#pragma unroll
            for (int i = 0; i < 4; ++i) aa[i] = Pt[t * 64 + ty * 4 + i];
            float4 bv0 = *(const float4*)&KVs[t * 64 + tx * 8];
            float4 bv1 = *(const float4*)&KVs[t * 64 + tx * 8 + 4];
            float bb[8] = {bv0.x, bv0.y, bv0.z, bv0.w, bv1.x, bv1.y, bv1.z, bv1.w};
#pragma unroll
            for (int i = 0; i < 4; ++i)
#pragma unroll
                for (int j = 0; j < 8; ++j)
                    acc[i][j] = fmaf(aa[i], bb[j], acc[i][j]);
        }
    }
    __syncthreads();  // last PV reads done; Pt reusable as reduction scratch

    // Reduce row sums across the 8 tx column-groups.
#pragma unroll
    for (int i = 0; i < 4; ++i)
        Pt[(ty * 4 + i) * 8 + tx] = rs[i];
    __syncthreads();

#pragma unroll
    for (int i = 0; i < 4; ++i) {
        const int q = ty * 4 + i;
        float tot = 0.0f;
#pragma unroll
        for (int x = 0; x < 8; ++x) tot += Pt[q * 8 + x];
        const float inv = 1.0f / (tot + 1e-8f);
        const int s = qt * 64 + q;
        float* op = out + ((size_t)b * NS + s) * ND + h * NHD + tx * 8;
        *(float4*)(op)     = make_float4(acc[i][0] * inv, acc[i][1] * inv,
                                         acc[i][2] * inv, acc[i][3] * inv);
        *(float4*)(op + 4) = make_float4(acc[i][4] * inv, acc[i][5] * inv,
                                         acc[i][6] * inv, acc[i][7] * inv);
    }
}

// ---------------------------------------------------------------------------
extern "C" void kernel_launch(void* const* d_in, const int* in_sizes, int n_in,
                              void* d_out, int out_size) {
    (void)in_sizes; (void)n_in; (void)out_size;
    const float* x    = (const float*)d_in[0];
    const float* mask = (const float*)d_in[1];
    const float* Wq   = (const float*)d_in[2];
    const float* Wk   = (const float*)d_in[3];
    const float* Wv   = (const float*)d_in[4];
    float* out = (float*)d_out;

    // Q/K/V projection: grid (N/128, M/128, 3)
    qkv_gemm<<<dim3(ND / 128, (NB * NS) / 128, 3), 256>>>(x, Wq, Wk, Wv);
    // Fused attention: grid (S/64, H, B)
    attn_fused<<<dim3(NS / 64, NH, NB), 128>>>(mask, out);
}

// round 5
// speedup vs baseline: 2.3160x; 2.3160x over previous
#include <cuda_runtime.h>
#include <cuda_bf16.h>
#include <stdint.h>

#define NB 8
#define NS 1024
#define ND 1024
#define NH 16
#define NHD 64

// Static device scratch (no runtime allocation). bf16 hi/lo split operands.
static __device__ __align__(16) __nv_bfloat16 g_qh[(size_t)NB * NH * NS * NHD];
static __device__ __align__(16) __nv_bfloat16 g_ql[(size_t)NB * NH * NS * NHD];
static __device__ __align__(16) __nv_bfloat16 g_kh[(size_t)NB * NH * NS * NHD];
static __device__ __align__(16) __nv_bfloat16 g_kl[(size_t)NB * NH * NS * NHD];
static __device__ __align__(16) __nv_bfloat16 g_vh[(size_t)NB * NH * NS * NHD];
static __device__ __align__(16) __nv_bfloat16 g_vl[(size_t)NB * NH * NS * NHD];
static __device__ __align__(16) uint8_t       g_m8[(size_t)NB * NS * NS];

// ---------------------------------------------------------------------------
// helpers
// ---------------------------------------------------------------------------
__device__ __forceinline__ uint32_t smem_u32(const void* p) {
    uint32_t a;
    asm("{ .reg .u64 t; cvta.to.shared.u64 t, %1; cvt.u32.u64 %0, t; }"
        : "=r"(a) : "l"(p));
    return a;
}
__device__ __forceinline__ void ldsm4(uint32_t* r, uint32_t a) {
    asm volatile("ldmatrix.sync.aligned.m8n8.x4.shared.b16 {%0,%1,%2,%3}, [%4];"
                 : "=r"(r[0]), "=r"(r[1]), "=r"(r[2]), "=r"(r[3]) : "r"(a));
}
__device__ __forceinline__ void ldsm2(uint32_t* r, uint32_t a) {
    asm volatile("ldmatrix.sync.aligned.m8n8.x2.shared.b16 {%0,%1}, [%2];"
                 : "=r"(r[0]), "=r"(r[1]) : "r"(a));
}
__device__ __forceinline__ void ldsm2t(uint32_t* r, uint32_t a) {
    asm volatile("ldmatrix.sync.aligned.m8n8.x2.trans.shared.b16 {%0,%1}, [%2];"
                 : "=r"(r[0]), "=r"(r[1]) : "r"(a));
}
// D += A(16x16) * B(16x8), bf16 in, fp32 accum
__device__ __forceinline__ void mma16816(float* c, const uint32_t* a, const uint32_t* b) {
    asm volatile(
        "mma.sync.aligned.m16n8k16.row.col.f32.bf16.bf16.f32 "
        "{%0,%1,%2,%3},{%4,%5,%6,%7},{%8,%9},{%0,%1,%2,%3};"
        : "+f"(c[0]), "+f"(c[1]), "+f"(c[2]), "+f"(c[3])
        : "r"(a[0]), "r"(a[1]), "r"(a[2]), "r"(a[3]), "r"(b[0]), "r"(b[1]));
}
__device__ __forceinline__ uint32_t pkb(__nv_bfloat16 a, __nv_bfloat16 b) {
    return (uint32_t)__bfloat16_as_ushort(a) | ((uint32_t)__bfloat16_as_ushort(b) << 16);
}
__device__ __forceinline__ __nv_bfloat16 bfh(float v) { return __float2bfloat16_rn(v); }
__device__ __forceinline__ __nv_bfloat16 bfl(float v, __nv_bfloat16 h) {
    return __float2bfloat16_rn(v - __bfloat162float(h));
}

// ---------------------------------------------------------------------------
// mask -> uint8
// ---------------------------------------------------------------------------
__global__ void prep_mask(const float* __restrict__ m) {
    size_t i = (size_t)blockIdx.x * 256 + threadIdx.x;
    float4 v = ((const float4*)m)[i];
    ((uchar4*)g_m8)[i] = make_uchar4(v.x != 0.f, v.y != 0.f, v.z != 0.f, v.w != 0.f);
}

// ---------------------------------------------------------------------------
// QKV GEMM: C = X @ W via bf16-split HMMA. Block 128x128, 8 warps (2x4),
// warp tile 64x32. K-chunk 32, register-prefetch double buffer.
// Epilogue: split to bf16 hi/lo, scatter [b,h,s,hd]; Q scaled by 1/8.
// ---------------------------------------------------------------------------
__global__ __launch_bounds__(256, 1)
void qkv_gemm_tc(const float* __restrict__ X, const float* __restrict__ Wq,
                 const float* __restrict__ Wk, const float* __restrict__ Wv) {
    __shared__ __nv_bfloat16 Ah[128 * 40], Al[128 * 40];
    __shared__ __nv_bfloat16 Bh[32 * 136], Bl[32 * 136];

    const int tid = threadIdx.x, lane = tid & 31, wid = tid >> 5;
    const int wm = wid >> 2, wn = wid & 3;
    const int z = blockIdx.z;
    const float* W = z == 0 ? Wq : (z == 1 ? Wk : Wv);
    const int m0 = blockIdx.y * 128, n0 = blockIdx.x * 128;

    const uint32_t ah_b = smem_u32(Ah), al_b = smem_u32(Al);
    const uint32_t bh_b = smem_u32(Bh), bl_b = smem_u32(Bl);

    const int am = tid >> 1, ac = (tid & 1) * 16;   // A: 128 rows x 32 cols
    const int bk = tid >> 3, bc = (tid & 7) * 16;   // B: 32 rows x 128 cols

    float acc[4][4][4] = {};
    float4 xa[4], wb[4];

    auto ldchunk = [&](int k0) {
#pragma unroll
        for (int i = 0; i < 4; ++i)
            xa[i] = *(const float4*)(X + (size_t)(m0 + am) * ND + k0 + ac + 4 * i);
#pragma unroll
        for (int i = 0; i < 4; ++i)
            wb[i] = *(const float4*)(W + (size_t)(k0 + bk) * ND + n0 + bc + 4 * i);
    };
    auto stchunk = [&]() {
#pragma unroll
        for (int i = 0; i < 4; ++i) {
            float4 v = xa[i];
            __nv_bfloat16 h0 = bfh(v.x), h1 = bfh(v.y), h2 = bfh(v.z), h3 = bfh(v.w);
            int idx = am * 40 + ac + 4 * i;
            ((uint32_t*)Ah)[idx >> 1] = pkb(h0, h1);
            ((uint32_t*)Ah)[(idx >> 1) + 1] = pkb(h2, h3);
            ((uint32_t*)Al)[idx >> 1] = pkb(bfl(v.x, h0), bfl(v.y, h1));
            ((uint32_t*)Al)[(idx >> 1) + 1] = pkb(bfl(v.z, h2), bfl(v.w, h3));
        }
#pragma unroll
        for (int i = 0; i < 4; ++i) {
            float4 v = wb[i];
            __nv_bfloat16 h0 = bfh(v.x), h1 = bfh(v.y), h2 = bfh(v.z), h3 = bfh(v.w);
            int idx = bk * 136 + bc + 4 * i;
            ((uint32_t*)Bh)[idx >> 1] = pkb(h0, h1);
            ((uint32_t*)Bh)[(idx >> 1) + 1] = pkb(h2, h3);
            ((uint32_t*)Bl)[idx >> 1] = pkb(bfl(v.x, h0), bfl(v.y, h1));
            ((uint32_t*)Bl)[(idx >> 1) + 1] = pkb(bfl(v.z, h2), bfl(v.w, h3));
        }
    };

    ldchunk(0);
    stchunk();
    __syncthreads();

    for (int k0 = 0; k0 < ND; k0 += 32) {
        const bool more = (k0 + 32 < ND);
        if (more) ldchunk(k0 + 32);   // LDGs overlap the MMAs below
#pragma unroll
        for (int kk = 0; kk < 32; kk += 16) {
            uint32_t a_h[4][4], a_l[4][4];
#pragma unroll
            for (int mt = 0; mt < 4; ++mt) {
                uint32_t off = ((wm * 64 + mt * 16 + (lane & 15)) * 40 +
                                kk + 8 * ((lane >> 4) & 1)) << 1;
                ldsm4(a_h[mt], ah_b + off);
                ldsm4(a_l[mt], al_b + off);
            }
#pragma unroll
            for (int nt = 0; nt < 4; ++nt) {
                uint32_t boff = (((kk + (lane & 15)) * 136) + wn * 32 + nt * 8) << 1;
                uint32_t b_h[2], b_l[2];
                ldsm2t(b_h, bh_b + boff);
                ldsm2t(b_l, bl_b + boff);
#pragma unroll
                for (int mt = 0; mt < 4; ++mt) {
                    mma16816(acc[mt][nt], a_h[mt], b_h);
                    mma16816(acc[mt][nt], a_h[mt], b_l);
                    mma16816(acc[mt][nt], a_l[mt], b_h);
                }
            }
        }
        __syncthreads();
        if (more) stchunk();
        __syncthreads();
    }

    // Epilogue: split + scatter to [b,h,s,hd]
    __nv_bfloat16 *dh, *dl;
    if (z == 0)      { dh = g_qh; dl = g_ql; }
    else if (z == 1) { dh = g_kh; dl = g_kl; }
    else             { dh = g_vh; dl = g_vl; }
    const float scale = (z == 0) ? 0.125f : 1.0f;
    const int g = lane >> 2, lam = lane & 3;
#pragma unroll
    for (int mt = 0; mt < 4; ++mt) {
#pragma unroll
        for (int nt = 0; nt < 4; ++nt) {
            const int n = n0 + wn * 32 + nt * 8 + lam * 2;
            const int h = n >> 6, hd = n & (NHD - 1);
#pragma unroll
            for (int rr = 0; rr < 2; ++rr) {
                const int m = m0 + wm * 64 + mt * 16 + g + rr * 8;
                const int b = m >> 10, s = m & (NS - 1);
                const float c0 = acc[mt][nt][rr * 2 + 0] * scale;
                const float c1 = acc[mt][nt][rr * 2 + 1] * scale;
                __nv_bfloat16 h0 = bfh(c0), h1 = bfh(c1);
                const size_t idx = (((size_t)b * NH + h) * NS + s) * NHD + hd;
                *(uint32_t*)(dh + idx) = pkb(h0, h1);
                *(uint32_t*)(dl + idx) = pkb(bfl(c0, h0), bfl(c1, h1));
            }
        }
    }
}

// ---------------------------------------------------------------------------
// Fused attention. Block = (64 q-rows, h, b), 4 warps (16 q-rows each).
// Q fragments register-resident; stream 64-key K/V tiles.
// S = Q K^T (split MMAs) -> exp*mask in regs -> P split in regs -> PV MMAs.
// ---------------------------------------------------------------------------
__global__ __launch_bounds__(128, 2)
void attn_tc(float* __restrict__ out) {
    __shared__ __nv_bfloat16 Ksh[64 * 72], Ksl[64 * 72];
    __shared__ __nv_bfloat16 Vsh[64 * 72], Vsl[64 * 72];

    const int tid = threadIdx.x, lane = tid & 31, wid = tid >> 5;
    const int qt = blockIdx.x, h = blockIdx.y, b = blockIdx.z;
    const size_t bh = (size_t)b * NH + h;
    const int g = lane >> 2, lam = lane & 3;

    const __nv_bfloat16* kh_g = g_kh + bh * NS * NHD;
    const __nv_bfloat16* kl_g = g_kl + bh * NS * NHD;
    const __nv_bfloat16* vh_g = g_vh + bh * NS * NHD;
    const __nv_bfloat16* vl_g = g_vl + bh * NS * NHD;

    const uint32_t ksh_b = smem_u32(Ksh), ksl_b = smem_u32(Ksl);
    const uint32_t vsh_b = smem_u32(Vsh), vsl_b = smem_u32(Vsl);

    // Stage Q tile into V smem region, build register fragments.
    {
        const int r = tid >> 1, c0 = (tid & 1) * 32;
        const size_t gq = (bh * NS + (size_t)qt * 64 + r) * NHD + c0;
#pragma unroll
        for (int i = 0; i < 4; ++i) {
            const uint32_t soff = (r * 72 + c0 + 8 * i) * 2;
            *(uint4*)((char*)Vsh + soff) = *(const uint4*)(g_qh + gq + 8 * i);
            *(uint4*)((char*)Vsl + soff) = *(const uint4*)(g_ql + gq + 8 * i);
        }
    }
    __syncthreads();
    uint32_t qfh[4][4], qfl[4][4];
#pragma unroll
    for (int dt = 0; dt < 4; ++dt) {
        const uint32_t off = ((wid * 16 + (lane & 15)) * 72 +
                              dt * 16 + 8 * ((lane >> 4) & 1)) << 1;
        ldsm4(qfh[dt], vsh_b + off);
        ldsm4(qfl[dt], vsl_b + off);
    }
    __syncthreads();   // all warps done with staged Q before V overwrite

    float ctx[8][4] = {};
    float rs0 = 0.f, rs1 = 0.f;
    const int q0 = qt * 64 + wid * 16 + g;
    const uint8_t* mrow0 = g_m8 + ((size_t)b * NS + q0) * NS;
    const uint8_t* mrow1 = mrow0 + 8 * NS;

    for (int kt = 0; kt < 16; ++kt) {
        __syncthreads();
        {   // load K/V tiles (bf16 hi/lo), coalesced 16B copies
            const int r = tid >> 1, c0 = (tid & 1) * 32;
            const size_t gi = ((size_t)(kt * 64 + r)) * NHD + c0;
#pragma unroll
            for (int i = 0; i < 4; ++i) {
                const uint32_t soff = (r * 72 + c0 + 8 * i) * 2;
                *(uint4*)((char*)Ksh + soff) = *(const uint4*)(kh_g + gi + 8 * i);
                *(uint4*)((char*)Ksl + soff) = *(const uint4*)(kl_g + gi + 8 * i);
                *(uint4*)((char*)Vsh + soff) = *(const uint4*)(vh_g + gi + 8 * i);
                *(uint4*)((char*)Vsl + soff) = *(const uint4*)(vl_g + gi + 8 * i);
            }
        }
        __syncthreads();

        // S = Q K^T
        float sacc[8][4] = {};
#pragma unroll
        for (int nt = 0; nt < 8; ++nt) {
#pragma unroll
            for (int dt = 0; dt < 4; ++dt) {
                const uint32_t boff = ((nt * 8 + (lane & 7)) * 72 +
                                       dt * 16 + 8 * ((lane >> 3) & 1)) << 1;
                uint32_t kb_h[2], kb_l[2];
                ldsm2(kb_h, ksh_b + boff);
                ldsm2(kb_l, ksl_b + boff);
                mma16816(sacc[nt], qfh[dt], kb_h);
                mma16816(sacc[nt], qfh[dt], kb_l);
                mma16816(sacc[nt], qfl[dt], kb_h);
            }
        }

        // P = exp(S)*mask, split to bf16 hi/lo A-fragments (in registers)
        uint32_t ph[4][4], pl[4][4];
#pragma unroll
        for (int dt = 0; dt < 4; ++dt) {
#pragma unroll
            for (int j = 0; j < 2; ++j) {
                const int nt = dt * 2 + j;
                const int t = kt * 64 + nt * 8 + lam * 2;
                const uchar2 mc0 = *(const uchar2*)(mrow0 + t);
                const uchar2 mc1 = *(const uchar2*)(mrow1 + t);
                const float p0 = __expf(sacc[nt][0]) * (float)mc0.x;
                const float p1 = __expf(sacc[nt][1]) * (float)mc0.y;
                const float p2 = __expf(sacc[nt][2]) * (float)mc1.x;
                const float p3 = __expf(sacc[nt][3]) * (float)mc1.y;
                rs0 += p0 + p1;
                rs1 += p2 + p3;
                __nv_bfloat16 h0 = bfh(p0), h1 = bfh(p1), h2 = bfh(p2), h3 = bfh(p3);
                ph[dt][2 * j + 0] = pkb(h0, h1);
                ph[dt][2 * j + 1] = pkb(h2, h3);
                pl[dt][2 * j + 0] = pkb(bfl(p0, h0), bfl(p1, h1));
                pl[dt][2 * j + 1] = pkb(bfl(p2, h2), bfl(p3, h3));
            }
        }

        // ctx += P V
#pragma unroll
        for (int nt = 0; nt < 8; ++nt) {
#pragma unroll
            for (int dt = 0; dt < 4; ++dt) {
                const uint32_t voff = ((dt * 16 + (lane & 15)) * 72 + nt * 8) << 1;
                uint32_t vb_h[2], vb_l[2];
                ldsm2t(vb_h, vsh_b + voff);
                ldsm2t(vb_l, vsl_b + voff);
                mma16816(ctx[nt], ph[dt], vb_h);
                mma16816(ctx[nt], ph[dt], vb_l);
                mma16816(ctx[nt], pl[dt], vb_h);
            }
        }
    }

    // rowsum reduction across the quad (lanes sharing groupID)
    rs0 += __shfl_xor_sync(0xffffffffu, rs0, 1);
    rs0 += __shfl_xor_sync(0xffffffffu, rs0, 2);
    rs1 += __shfl_xor_sync(0xffffffffu, rs1, 1);
    rs1 += __shfl_xor_sync(0xffffffffu, rs1, 2);
    const float inv0 = 1.0f / (rs0 + 1e-8f);
    const float inv1 = 1.0f / (rs1 + 1e-8f);

#pragma unroll
    for (int nt = 0; nt < 8; ++nt) {
        const int d = nt * 8 + lam * 2;
        float* o0 = out + ((size_t)b * NS + q0) * ND + h * NHD + d;
        *(float2*)o0 = make_float2(ctx[nt][0] * inv0, ctx[nt][1] * inv0);
        *(float2*)(o0 + (size_t)8 * ND) =
            make_float2(ctx[nt][2] * inv1, ctx[nt][3] * inv1);
    }
}

// ---------------------------------------------------------------------------
extern "C" void kernel_launch(void* const* d_in, const int* in_sizes, int n_in,
                              void* d_out, int out_size) {
    (void)in_sizes; (void)n_in; (void)out_size;
    const float* x    = (const float*)d_in[0];
    const float* mask = (const float*)d_in[1];
    const float* Wq   = (const float*)d_in[2];
    const float* Wk   = (const float*)d_in[3];
    const float* Wv   = (const float*)d_in[4];
    float* out = (float*)d_out;

    prep_mask<<<(NB * NS * NS) / (4 * 256), 256>>>(mask);
    qkv_gemm_tc<<<dim3(ND / 128, (NB * NS) / 128, 3), 256>>>(x, Wq, Wk, Wv);
    attn_tc<<<dim3(NS / 64, NH, NB), 128>>>(out);
}

// round 6
// speedup vs baseline: 2.7236x; 1.1760x over previous
#include <cuda_runtime.h>
#include <cuda_bf16.h>
#include <stdint.h>

#define NB 8
#define NS 1024
#define ND 1024
#define NH 16
#define NHD 64

// Static device scratch. bf16 hi/lo split operands.
static __device__ __align__(16) __nv_bfloat16 g_xh[(size_t)NB * NS * ND];
static __device__ __align__(16) __nv_bfloat16 g_xl[(size_t)NB * NS * ND];
static __device__ __align__(16) __nv_bfloat16 g_wh[3][(size_t)ND * ND];
static __device__ __align__(16) __nv_bfloat16 g_wl[3][(size_t)ND * ND];
static __device__ __align__(16) __nv_bfloat16 g_qh[(size_t)NB * NH * NS * NHD];
static __device__ __align__(16) __nv_bfloat16 g_ql[(size_t)NB * NH * NS * NHD];
static __device__ __align__(16) __nv_bfloat16 g_kh[(size_t)NB * NH * NS * NHD];
static __device__ __align__(16) __nv_bfloat16 g_kl[(size_t)NB * NH * NS * NHD];
static __device__ __align__(16) __nv_bfloat16 g_vh[(size_t)NB * NH * NS * NHD];
static __device__ __align__(16) __nv_bfloat16 g_vl[(size_t)NB * NH * NS * NHD];
static __device__ __align__(16) uint8_t       g_m8[(size_t)NB * NS * NS];

// ---------------------------------------------------------------------------
__device__ __forceinline__ uint32_t smem_u32(const void* p) {
    uint32_t a;
    asm("{ .reg .u64 t; cvta.to.shared.u64 t, %1; cvt.u32.u64 %0, t; }"
        : "=r"(a) : "l"(p));
    return a;
}
__device__ __forceinline__ void ldsm4(uint32_t* r, uint32_t a) {
    asm volatile("ldmatrix.sync.aligned.m8n8.x4.shared.b16 {%0,%1,%2,%3}, [%4];"
                 : "=r"(r[0]), "=r"(r[1]), "=r"(r[2]), "=r"(r[3]) : "r"(a));
}
__device__ __forceinline__ void ldsm4t(uint32_t* r, uint32_t a) {
    asm volatile("ldmatrix.sync.aligned.m8n8.x4.trans.shared.b16 {%0,%1,%2,%3}, [%4];"
                 : "=r"(r[0]), "=r"(r[1]), "=r"(r[2]), "=r"(r[3]) : "r"(a));
}
__device__ __forceinline__ void mma16816(float* c, const uint32_t* a,
                                         uint32_t b0, uint32_t b1) {
    asm volatile(
        "mma.sync.aligned.m16n8k16.row.col.f32.bf16.bf16.f32 "
        "{%0,%1,%2,%3},{%4,%5,%6,%7},{%8,%9},{%0,%1,%2,%3};"
        : "+f"(c[0]), "+f"(c[1]), "+f"(c[2]), "+f"(c[3])
        : "r"(a[0]), "r"(a[1]), "r"(a[2]), "r"(a[3]), "r"(b0), "r"(b1));
}
#define CPA16(s, g) \
    asm volatile("cp.async.cg.shared.global [%0], [%1], 16;" :: "r"(s), "l"(g))
#define CPC()  asm volatile("cp.async.commit_group;" ::: "memory")
#define CPW0() asm volatile("cp.async.wait_group 0;" ::: "memory")

__device__ __forceinline__ uint32_t pkb(__nv_bfloat16 a, __nv_bfloat16 b) {
    return (uint32_t)__bfloat16_as_ushort(a) | ((uint32_t)__bfloat16_as_ushort(b) << 16);
}
__device__ __forceinline__ __nv_bfloat16 bfh(float v) { return __float2bfloat16_rn(v); }
__device__ __forceinline__ __nv_bfloat16 bfl(float v, __nv_bfloat16 h) {
    return __float2bfloat16_rn(v - __bfloat162float(h));
}

// ---------------------------------------------------------------------------
// prep: mask->u8, x->hi/lo, W->hi/lo
// ---------------------------------------------------------------------------
__global__ void prep_mask(const float* __restrict__ m) {
    size_t i = (size_t)blockIdx.x * 256 + threadIdx.x;
    float4 v = ((const float4*)m)[i];
    ((uchar4*)g_m8)[i] = make_uchar4(v.x != 0.f, v.y != 0.f, v.z != 0.f, v.w != 0.f);
}
__device__ __forceinline__ void split_store(const float* src, __nv_bfloat16* dh,
                                            __nv_bfloat16* dl, size_t i) {
    float4 v = ((const float4*)src)[i];
    __nv_bfloat16 h0 = bfh(v.x), h1 = bfh(v.y), h2 = bfh(v.z), h3 = bfh(v.w);
    ((uint32_t*)dh)[2 * i]     = pkb(h0, h1);
    ((uint32_t*)dh)[2 * i + 1] = pkb(h2, h3);
    ((uint32_t*)dl)[2 * i]     = pkb(bfl(v.x, h0), bfl(v.y, h1));
    ((uint32_t*)dl)[2 * i + 1] = pkb(bfl(v.z, h2), bfl(v.w, h3));
}
__global__ void prep_x(const float* __restrict__ x) {
    split_store(x, g_xh, g_xl, (size_t)blockIdx.x * 256 + threadIdx.x);
}
__global__ void prep_w(const float* __restrict__ Wq, const float* __restrict__ Wk,
                       const float* __restrict__ Wv) {
    const float* W = blockIdx.y == 0 ? Wq : (blockIdx.y == 1 ? Wk : Wv);
    split_store(W, g_wh[blockIdx.y], g_wl[blockIdx.y],
                (size_t)blockIdx.x * 256 + threadIdx.x);
}

// ---------------------------------------------------------------------------
// QKV GEMM: C = X @ W (3x bf16-split HMMA). Block 128x128, 8 warps (2x4),
// K-chunk 16, cp.async double buffer. Epilogue splits to [b,h,s,hd]; Q *= 1/8.
// ---------------------------------------------------------------------------
__global__ __launch_bounds__(256, 1)
void qkv_gemm_tc() {
    __shared__ __nv_bfloat16 Ah[2][128 * 24], Al[2][128 * 24];
    __shared__ __nv_bfloat16 Bh[2][16 * 136], Bl[2][16 * 136];

    const int tid = threadIdx.x, lane = tid & 31, wid = tid >> 5;
    const int wm = wid >> 2, wn = wid & 3;
    const int z = blockIdx.z;
    const int m0 = blockIdx.y * 128, n0 = blockIdx.x * 128;
    const __nv_bfloat16* wh = g_wh[z];
    const __nv_bfloat16* wl = g_wl[z];

    // copy mapping
    const int ar = tid >> 1, ac = (tid & 1) * 8;     // A: 128r x 16c
    const int br = tid >> 4, bc = (tid & 15) * 8;    // B: 16r x 128c
    const size_t ga = (size_t)(m0 + ar) * ND + ac;
    const size_t gb = (size_t)br * ND + n0 + bc;

    auto preload = [&](int c, int st) {
        const size_t ka = ga + c * 16;
        const size_t kb = gb + (size_t)c * 16 * ND;
        CPA16(smem_u32(&Ah[st][ar * 24 + ac]), g_xh + ka);
        CPA16(smem_u32(&Al[st][ar * 24 + ac]), g_xl + ka);
        CPA16(smem_u32(&Bh[st][br * 136 + bc]), wh + kb);
        CPA16(smem_u32(&Bl[st][br * 136 + bc]), wl + kb);
    };

    float acc[4][4][4] = {};
    preload(0, 0);
    CPC();

    for (int c = 0; c < 64; ++c) {
        const int st = c & 1;
        CPW0();
        __syncthreads();
        if (c + 1 < 64) { preload(c + 1, st ^ 1); CPC(); }

        uint32_t ah_f[4][4], al_f[4][4];
#pragma unroll
        for (int mt = 0; mt < 4; ++mt) {
            const uint32_t off =
                smem_u32(&Ah[st][(wm * 64 + mt * 16 + (lane & 15)) * 24 +
                                 8 * ((lane >> 4) & 1)]);
            ldsm4(ah_f[mt], off);
            ldsm4(al_f[mt], off + (uint32_t)((char*)Al - (char*)Ah));
        }
#pragma unroll
        for (int ntp = 0; ntp < 2; ++ntp) {
            const uint32_t boff =
                smem_u32(&Bh[st][(lane & 15) * 136 + wn * 32 + ntp * 16 +
                                 8 * ((lane >> 4) & 1)]);
            uint32_t bh_r[4], bl_r[4];
            ldsm4t(bh_r, boff);
            ldsm4t(bl_r, boff + (uint32_t)((char*)Bl - (char*)Bh));
#pragma unroll
            for (int mt = 0; mt < 4; ++mt) {
                float* c0 = acc[mt][2 * ntp];
                float* c1 = acc[mt][2 * ntp + 1];
                mma16816(c0, ah_f[mt], bh_r[0], bh_r[1]);
                mma16816(c0, ah_f[mt], bl_r[0], bl_r[1]);
                mma16816(c0, al_f[mt], bh_r[0], bh_r[1]);
                mma16816(c1, ah_f[mt], bh_r[2], bh_r[3]);
                mma16816(c1, ah_f[mt], bl_r[2], bl_r[3]);
                mma16816(c1, al_f[mt], bh_r[2], bh_r[3]);
            }
        }
    }

    // Epilogue: split + scatter to [b,h,s,hd]
    __nv_bfloat16 *dh, *dl;
    if (z == 0)      { dh = g_qh; dl = g_ql; }
    else if (z == 1) { dh = g_kh; dl = g_kl; }
    else             { dh = g_vh; dl = g_vl; }
    const float scale = (z == 0) ? 0.125f : 1.0f;
    const int g = lane >> 2, lam = lane & 3;
#pragma unroll
    for (int mt = 0; mt < 4; ++mt)
#pragma unroll
        for (int nt = 0; nt < 4; ++nt) {
            const int n = n0 + wn * 32 + nt * 8 + lam * 2;
            const int h = n >> 6, hd = n & (NHD - 1);
#pragma unroll
            for (int rr = 0; rr < 2; ++rr) {
                const int m = m0 + wm * 64 + mt * 16 + g + rr * 8;
                const int b = m >> 10, s = m & (NS - 1);
                const float c0 = acc[mt][nt][rr * 2 + 0] * scale;
                const float c1 = acc[mt][nt][rr * 2 + 1] * scale;
                __nv_bfloat16 h0 = bfh(c0), h1 = bfh(c1);
                const size_t idx = (((size_t)b * NH + h) * NS + s) * NHD + hd;
                *(uint32_t*)(dh + idx) = pkb(h0, h1);
                *(uint32_t*)(dl + idx) = pkb(bfl(c0, h0), bfl(c1, h1));
            }
        }
}

// ---------------------------------------------------------------------------
// Fused attention. Block = 64 q-rows x (h,b); 4 warps x 16 q-rows.
// Q frags direct from global; K/V stream in 32-key cp.async double buffer.
// ---------------------------------------------------------------------------
__global__ __launch_bounds__(128, 3)
void attn_tc(float* __restrict__ out) {
    __shared__ __nv_bfloat16 Ksh[2][32 * 72], Ksl[2][32 * 72];
    __shared__ __nv_bfloat16 Vsh[2][32 * 72], Vsl[2][32 * 72];

    const int tid = threadIdx.x, lane = tid & 31, wid = tid >> 5;
    const int qt = blockIdx.x, h = blockIdx.y, b = blockIdx.z;
    const size_t bh = (size_t)b * NH + h;
    const int g = lane >> 2, lam = lane & 3;

    const __nv_bfloat16* kh_g = g_kh + bh * NS * NHD;
    const __nv_bfloat16* kl_g = g_kl + bh * NS * NHD;
    const __nv_bfloat16* vh_g = g_vh + bh * NS * NHD;
    const __nv_bfloat16* vl_g = g_vl + bh * NS * NHD;

    // Q fragments straight from global (frag layout == memory layout).
    uint32_t qfh[4][4], qfl[4][4];
    {
        const __nv_bfloat16* qh_g = g_qh + (bh * NS + (size_t)qt * 64) * NHD;
        const __nv_bfloat16* ql_g = g_ql + (bh * NS + (size_t)qt * 64) * NHD;
        const int r0 = wid * 16 + g, r1 = r0 + 8;
#pragma unroll
        for (int dt = 0; dt < 4; ++dt) {
            const int c = dt * 16 + lam * 2;
            qfh[dt][0] = *(const uint32_t*)(qh_g + (size_t)r0 * NHD + c);
            qfh[dt][1] = *(const uint32_t*)(qh_g + (size_t)r1 * NHD + c);
            qfh[dt][2] = *(const uint32_t*)(qh_g + (size_t)r0 * NHD + c + 8);
            qfh[dt][3] = *(const uint32_t*)(qh_g + (size_t)r1 * NHD + c + 8);
            qfl[dt][0] = *(const uint32_t*)(ql_g + (size_t)r0 * NHD + c);
            qfl[dt][1] = *(const uint32_t*)(ql_g + (size_t)r1 * NHD + c);
            qfl[dt][2] = *(const uint32_t*)(ql_g + (size_t)r0 * NHD + c + 8);
            qfl[dt][3] = *(const uint32_t*)(ql_g + (size_t)r1 * NHD + c + 8);
        }
    }

    // cp.async copy mapping: per array 32r x 64c bf16; 2 x 16B per thread.
    auto preload = [&](int kt, int st) {
#pragma unroll
        for (int i = 0; i < 2; ++i) {
            const int idx = tid * 2 + i;
            const int r = idx >> 3, c8 = (idx & 7) * 8;
            const size_t gi = (size_t)(kt * 32 + r) * NHD + c8;
            const uint32_t so = smem_u32(&Ksh[st][r * 72 + c8]);
            const uint32_t d  = (uint32_t)((char*)Ksl - (char*)Ksh);
            const uint32_t dv = (uint32_t)((char*)Vsh - (char*)Ksh);
            const uint32_t dl2 = (uint32_t)((char*)Vsl - (char*)Ksh);
            CPA16(so,       kh_g + gi);
            CPA16(so + d,   kl_g + gi);
            CPA16(so + dv,  vh_g + gi);
            CPA16(so + dl2, vl_g + gi);
        }
    };

    float ctx[8][4] = {};
    float rs0 = 0.f, rs1 = 0.f;
    const int q0 = qt * 64 + wid * 16 + g;
    const uint8_t* mrow0 = g_m8 + ((size_t)b * NS + q0) * NS;
    const uint8_t* mrow1 = mrow0 + 8 * NS;

    preload(0, 0);
    CPC();

    for (int kts = 0; kts < 32; ++kts) {
        const int st = kts & 1;
        CPW0();
        __syncthreads();
        if (kts + 1 < 32) { preload(kts + 1, st ^ 1); CPC(); }

        // S = Q K^T over this 32-key stage
        float sacc[4][4] = {};
#pragma unroll
        for (int ntp = 0; ntp < 2; ++ntp) {
#pragma unroll
            for (int dt = 0; dt < 4; ++dt) {
                const uint32_t boff = smem_u32(
                    &Ksh[st][(ntp * 16 + 8 * ((lane >> 4) & 1) + (lane & 7)) * 72 +
                             dt * 16 + 8 * ((lane >> 3) & 1)]);
                uint32_t kb_h[4], kb_l[4];
                ldsm4(kb_h, boff);
                ldsm4(kb_l, boff + (uint32_t)((char*)Ksl - (char*)Ksh));
                float* s0 = sacc[2 * ntp];
                float* s1 = sacc[2 * ntp + 1];
                mma16816(s0, qfh[dt], kb_h[0], kb_h[1]);
                mma16816(s0, qfh[dt], kb_l[0], kb_l[1]);
                mma16816(s0, qfl[dt], kb_h[0], kb_h[1]);
                mma16816(s1, qfh[dt], kb_h[2], kb_h[3]);
                mma16816(s1, qfh[dt], kb_l[2], kb_l[3]);
                mma16816(s1, qfl[dt], kb_h[2], kb_h[3]);
            }
        }

        // P = exp(S)*mask -> split A-fragments (registers only)
        uint32_t pah[2][4], pal[2][4];
#pragma unroll
        for (int nt = 0; nt < 4; ++nt) {
            const int t = kts * 32 + nt * 8 + lam * 2;
            const uchar2 mc0 = *(const uchar2*)(mrow0 + t);
            const uchar2 mc1 = *(const uchar2*)(mrow1 + t);
            const float p0 = __expf(sacc[nt][0]) * (float)mc0.x;
            const float p1 = __expf(sacc[nt][1]) * (float)mc0.y;
            const float p2 = __expf(sacc[nt][2]) * (float)mc1.x;
            const float p3 = __expf(sacc[nt][3]) * (float)mc1.y;
            rs0 += p0 + p1;
            rs1 += p2 + p3;
            __nv_bfloat16 h0 = bfh(p0), h1 = bfh(p1), h2 = bfh(p2), h3 = bfh(p3);
            const int j = nt >> 1, o = (nt & 1) * 2;
            pah[j][o + 0] = pkb(h0, h1);
            pah[j][o + 1] = pkb(h2, h3);
            pal[j][o + 0] = pkb(bfl(p0, h0), bfl(p1, h1));
            pal[j][o + 1] = pkb(bfl(p2, h2), bfl(p3, h3));
        }

        // ctx += P V
#pragma unroll
        for (int ntp = 0; ntp < 4; ++ntp) {
#pragma unroll
            for (int j = 0; j < 2; ++j) {
                const uint32_t voff = smem_u32(
                    &Vsh[st][(j * 16 + (lane & 15)) * 72 + ntp * 16 +
                             8 * ((lane >> 4) & 1)]);
                uint32_t vb_h[4], vb_l[4];
                ldsm4t(vb_h, voff);
                ldsm4t(vb_l, voff + (uint32_t)((char*)Vsl - (char*)Vsh));
                float* c0 = ctx[2 * ntp];
                float* c1 = ctx[2 * ntp + 1];
                mma16816(c0, pah[j], vb_h[0], vb_h[1]);
                mma16816(c0, pah[j], vb_l[0], vb_l[1]);
                mma16816(c0, pal[j], vb_h[0], vb_h[1]);
                mma16816(c1, pah[j], vb_h[2], vb_h[3]);
                mma16816(c1, pah[j], vb_l[2], vb_l[3]);
                mma16816(c1, pal[j], vb_h[2], vb_h[3]);
            }
        }
    }

    // rowsum reduction across the quad
    rs0 += __shfl_xor_sync(0xffffffffu, rs0, 1);
    rs0 += __shfl_xor_sync(0xffffffffu, rs0, 2);
    rs1 += __shfl_xor_sync(0xffffffffu, rs1, 1);
    rs1 += __shfl_xor_sync(0xffffffffu, rs1, 2);
    const float inv0 = 1.0f / (rs0 + 1e-8f);
    const float inv1 = 1.0f / (rs1 + 1e-8f);

#pragma unroll
    for (int nt = 0; nt < 8; ++nt) {
        const int d = nt * 8 + lam * 2;
        float* o0 = out + ((size_t)b * NS + q0) * ND + h * NHD + d;
        *(float2*)o0 = make_float2(ctx[nt][0] * inv0, ctx[nt][1] * inv0);
        *(float2*)(o0 + (size_t)8 * ND) =
            make_float2(ctx[nt][2] * inv1, ctx[nt][3] * inv1);
    }
}

// ---------------------------------------------------------------------------
extern "C" void kernel_launch(void* const* d_in, const int* in_sizes, int n_in,
                              void* d_out, int out_size) {
    (void)in_sizes; (void)n_in; (void)out_size;
    const float* x    = (const float*)d_in[0];
    const float* mask = (const float*)d_in[1];
    const float* Wq   = (const float*)d_in[2];
    const float* Wk   = (const float*)d_in[3];
    const float* Wv   = (const float*)d_in[4];
    float* out = (float*)d_out;

    prep_mask<<<(NB * NS * NS) / 1024, 256>>>(mask);
    prep_x<<<(NB * NS * ND) / 1024, 256>>>(x);
    prep_w<<<dim3((ND * ND) / 1024, 3), 256>>>(Wq, Wk, Wv);
    qkv_gemm_tc<<<dim3(ND / 128, (NB * NS) / 128, 3), 256>>>();
    attn_tc<<<dim3(NS / 64, NH, NB), 128>>>(out);
}